// round 4
// baseline (speedup 1.0000x reference)
#include <cuda_runtime.h>
#include <cstdint>
#include <cstddef>

// ---------------------------------------------------------------------------
// Problem constants
// ---------------------------------------------------------------------------
#define NF 100000
#define NE 200000
#define HID 128
#define RAW 512
#define NEDGE 1000000

// ---------------------------------------------------------------------------
// Scratch (device globals -- no allocation allowed)
// ---------------------------------------------------------------------------
__device__ float g_x_fr[(size_t)NF * HID];
__device__ float g_x_fe[(size_t)NE * HID];
__device__ float g_h_fr[(size_t)NF * HID];
__device__ float g_h_fe[(size_t)NE * HID];
__device__ float g_aggF[(size_t)NF * 256];   // [FF | EF] per fr-dst row
__device__ float g_aggE[(size_t)NE * 256];   // [FE | EE] per fe-dst row
// int degree buffer, layout (same as float norms):
// [dout_ff NF][din_ff NF][dout_fE NF][din_ef NF][din_fE NE][dout_ef NE][dout_ee NE][din_ee NE]
__device__ int   g_ideg[(size_t)4 * NF + (size_t)4 * NE];
__device__ float g_deg[(size_t)4 * NF + (size_t)4 * NE];   // rsqrt norms
__device__ float g_WcatF[(size_t)256 * HID];
__device__ float g_WcatE[(size_t)256 * HID];
__device__ float g_bias_gF[HID];
__device__ float g_bias_gE[HID];
// CSR (dst-sorted src lists) per relation
__device__ int g_csr_ff[NEDGE];
__device__ int g_csr_ef[NEDGE];
__device__ int g_csr_fE[NEDGE];
__device__ int g_csr_ee[NEDGE];
__device__ int g_row_ff[NF];  __device__ int g_cur_ff[NF];
__device__ int g_row_ef[NF];  __device__ int g_cur_ef[NF];
__device__ int g_row_fE[NE];  __device__ int g_cur_fE[NE];
__device__ int g_row_ee[NE];  __device__ int g_cur_ee[NE];
__device__ int g_part[NE];        // scan partials (max n = NE)
__device__ int g_bsum[1024];      // scan block sums

// ---------------------------------------------------------------------------
// Helpers
// ---------------------------------------------------------------------------
__device__ __forceinline__ uint32_t smem_u32(const void* p) {
    uint32_t r;
    asm("{ .reg .u64 t; cvta.to.shared.u64 t, %1; cvt.u32.u64 %0, t; }"
        : "=r"(r) : "l"(p));
    return r;
}

__device__ __forceinline__ uint32_t f2tf32(float f) {
    uint32_t u;
    asm("cvt.rna.tf32.f32 %0, %1;" : "=r"(u) : "f"(f));
    return u;
}

// ---------------------------------------------------------------------------
// Utility kernels
// ---------------------------------------------------------------------------
__global__ void zero_kernel(float* __restrict__ p, size_t n4) {
    size_t i = (size_t)blockIdx.x * blockDim.x + threadIdx.x;
    if (i < n4) ((float4*)p)[i] = make_float4(0.f, 0.f, 0.f, 0.f);
}

__global__ void deg_kernel(const int* __restrict__ src, const int* __restrict__ dst,
                           int* __restrict__ dout, int* __restrict__ din, int n) {
    int i = blockIdx.x * blockDim.x + threadIdx.x;
    if (i < n) {
        atomicAdd(&dout[src[i]], 1);
        atomicAdd(&din[dst[i]], 1);
    }
}

__global__ void norm_kernel(const int* __restrict__ d, float* __restrict__ p, int n) {
    int i = blockIdx.x * blockDim.x + threadIdx.x;
    if (i < n) {
        int v = d[i];
        p[i] = (v > 0) ? rsqrtf((float)v) : 0.f;
    }
}

__global__ void concat_kernel(const float* __restrict__ W1, const float* __restrict__ W2,
                              float* __restrict__ out) {
    int idx = blockIdx.x * blockDim.x + threadIdx.x;
    if (idx < 256 * 128) {
        int k = idx >> 7, n = idx & 127;
        out[idx] = (k < 128) ? W1[(size_t)k * 128 + n] : W2[(size_t)(k - 128) * 128 + n];
    }
}

__global__ void bias_combine_kernel(const float* __restrict__ b1,
                                    const float* __restrict__ b2,
                                    float* __restrict__ out, float alpha) {
    int i = blockIdx.x * blockDim.x + threadIdx.x;
    if (i < HID) out[i] = alpha * (b1[i] + b2[i]);
}

// ---------------------------------------------------------------------------
// Exclusive scan (3-phase) for row offsets; nb <= 1024
// ---------------------------------------------------------------------------
__global__ void scan_partial(const int* __restrict__ in, int* __restrict__ part,
                             int* __restrict__ bsum, int n) {
    __shared__ int sh[256];
    int t = threadIdx.x;
    int i = blockIdx.x * 256 + t;
    int v = (i < n) ? in[i] : 0;
    sh[t] = v;
    __syncthreads();
#pragma unroll
    for (int off = 1; off < 256; off <<= 1) {
        int u = (t >= off) ? sh[t - off] : 0;
        __syncthreads();
        sh[t] += u;
        __syncthreads();
    }
    if (i < n) part[i] = sh[t] - v;            // exclusive
    if (t == 255) bsum[blockIdx.x] = sh[255];  // block total
}

__global__ void scan_bsum(int* __restrict__ bsum, int nb) {
    __shared__ int sh[1024];
    int t = threadIdx.x;
    int v = (t < nb) ? bsum[t] : 0;
    sh[t] = v;
    __syncthreads();
#pragma unroll
    for (int off = 1; off < 1024; off <<= 1) {
        int u = (t >= off) ? sh[t - off] : 0;
        __syncthreads();
        sh[t] += u;
        __syncthreads();
    }
    if (t < nb) bsum[t] = sh[t] - v;           // exclusive block offsets
}

__global__ void scan_add(const int* __restrict__ part, const int* __restrict__ bsum,
                         int* __restrict__ row, int* __restrict__ cur, int n) {
    int i = blockIdx.x * 256 + threadIdx.x;
    if (i < n) {
        int v = part[i] + bsum[blockIdx.x];
        row[i] = v;
        cur[i] = v;
    }
}

__global__ void fill_kernel(const int* __restrict__ src, const int* __restrict__ dst,
                            int* __restrict__ cur, int* __restrict__ csr, int n) {
    int i = blockIdx.x * blockDim.x + threadIdx.x;
    if (i < n) {
        int pos = atomicAdd(&cur[dst[i]], 1);
        csr[pos] = src[i];
    }
}

// ---------------------------------------------------------------------------
// Gather aggregation: one warp per dst node, both relations fused.
// agg[i][0:128]   = nd1[i] * sum_{e in csr1(i)} x1[s_e] * ns1[s_e]
// agg[i][128:256] = nd2[i] * sum_{e in csr2(i)} x2[s_e] * ns2[s_e]
// ---------------------------------------------------------------------------
__global__ void __launch_bounds__(256)
gather_kernel(const float* __restrict__ x1, const int* __restrict__ csr1,
              const int* __restrict__ row1, const int* __restrict__ deg1,
              const float* __restrict__ ns1, const float* __restrict__ nd1,
              const float* __restrict__ x2, const int* __restrict__ csr2,
              const int* __restrict__ row2, const int* __restrict__ deg2,
              const float* __restrict__ ns2, const float* __restrict__ nd2,
              float* __restrict__ agg, int n) {
    int warp = (blockIdx.x * blockDim.x + threadIdx.x) >> 5;
    if (warp >= n) return;
    int lane = threadIdx.x & 31;

    float4 a1 = make_float4(0.f, 0.f, 0.f, 0.f);
    {
        int start = row1[warp], dc = deg1[warp];
        for (int base = 0; base < dc; base += 32) {
            int e = base + lane;
            int sidx = 0; float wv = 0.f;
            if (e < dc) { sidx = csr1[start + e]; wv = __ldg(&ns1[sidx]); }
            int m = min(32, dc - base);
            for (int j = 0; j < m; j++) {
                int s = __shfl_sync(0xffffffffu, sidx, j);
                float w = __shfl_sync(0xffffffffu, wv, j);
                float4 v = __ldg(&((const float4*)(x1 + (size_t)s * HID))[lane]);
                a1.x += v.x * w; a1.y += v.y * w; a1.z += v.z * w; a1.w += v.w * w;
            }
        }
        float s1 = nd1[warp];
        a1.x *= s1; a1.y *= s1; a1.z *= s1; a1.w *= s1;
    }
    float4 a2 = make_float4(0.f, 0.f, 0.f, 0.f);
    {
        int start = row2[warp], dc = deg2[warp];
        for (int base = 0; base < dc; base += 32) {
            int e = base + lane;
            int sidx = 0; float wv = 0.f;
            if (e < dc) { sidx = csr2[start + e]; wv = __ldg(&ns2[sidx]); }
            int m = min(32, dc - base);
            for (int j = 0; j < m; j++) {
                int s = __shfl_sync(0xffffffffu, sidx, j);
                float w = __shfl_sync(0xffffffffu, wv, j);
                float4 v = __ldg(&((const float4*)(x2 + (size_t)s * HID))[lane]);
                a2.x += v.x * w; a2.y += v.y * w; a2.z += v.z * w; a2.w += v.w * w;
            }
        }
        float s2 = nd2[warp];
        a2.x *= s2; a2.y *= s2; a2.z *= s2; a2.w *= s2;
    }
    float* ap = agg + (size_t)warp * 256;
    ((float4*)ap)[lane] = a1;
    ((float4*)(ap + 128))[lane] = a2;
}

// ---------------------------------------------------------------------------
// TF32 mma.sync GEMM:  C = epi( alpha * (A @ B) + bias )
//   A: [M][K] fp32 row-major      B: [K][ldB] fp32 row-major (native weights)
// Tile 128x128, BK=16, 8 warps (each 32x64), cp.async double buffer.
// EPI: 0 = store, 1 = relu, 2 = +resid
// ---------------------------------------------------------------------------
template <int EPI>
__global__ void __launch_bounds__(256, 2)
mma_gemm(const float* __restrict__ A, const float* __restrict__ B,
         const float* __restrict__ bias, const float* __restrict__ resid,
         float* __restrict__ C, int M, int K, int ldB, int ldC, float alpha) {
    __shared__ float As[2][128][20];
    __shared__ float Bs[2][16][136];

    const int tid = threadIdx.x;
    const int wid = tid >> 5;
    const int lane = tid & 31;
    const int g = lane >> 2;
    const int tig = lane & 3;
    const int warp_m = (wid & 3) * 32;
    const int warp_n = (wid >> 2) * 64;
    const int row0 = blockIdx.x * 128;
    const int n0 = blockIdx.y * 128;

    float c[2][8][4];
#pragma unroll
    for (int mt = 0; mt < 2; mt++)
#pragma unroll
        for (int nt = 0; nt < 8; nt++)
#pragma unroll
            for (int q = 0; q < 4; q++) c[mt][nt][q] = 0.f;

    const int NIT = K >> 4;

    auto load_stage = [&](int s, int k0) {
#pragma unroll
        for (int i = 0; i < 2; i++) {
            int cid = tid + i * 256;
            int m = cid >> 2, kc = (cid & 3) << 2;
            const float* src = A + (size_t)(row0 + m) * K + k0 + kc;
            uint32_t dst = smem_u32(&As[s][m][kc]);
            unsigned sz = (row0 + m < M) ? 16u : 0u;
            asm volatile("cp.async.cg.shared.global [%0], [%1], 16, %2;"
                         :: "r"(dst), "l"(src), "r"(sz));
        }
#pragma unroll
        for (int i = 0; i < 2; i++) {
            int cid = tid + i * 256;
            int k = cid >> 5, nch = (cid & 31) << 2;
            const float* src = B + (size_t)(k0 + k) * ldB + n0 + nch;
            uint32_t dst = smem_u32(&Bs[s][k][nch]);
            asm volatile("cp.async.cg.shared.global [%0], [%1], 16;"
                         :: "r"(dst), "l"(src));
        }
        asm volatile("cp.async.commit_group;");
    };

    load_stage(0, 0);

    for (int it = 0; it < NIT; it++) {
        int s = it & 1;
        if (it + 1 < NIT) {
            load_stage(s ^ 1, (it + 1) << 4);
            asm volatile("cp.async.wait_group 1;");
        } else {
            asm volatile("cp.async.wait_group 0;");
        }
        __syncthreads();

#pragma unroll
        for (int ks = 0; ks < 2; ks++) {
            const int kb = ks << 3;
            uint32_t a[2][4];
#pragma unroll
            for (int mt = 0; mt < 2; mt++) {
                int mr = warp_m + mt * 16 + g;
                a[mt][0] = f2tf32(As[s][mr][kb + tig]);
                a[mt][1] = f2tf32(As[s][mr + 8][kb + tig]);
                a[mt][2] = f2tf32(As[s][mr][kb + tig + 4]);
                a[mt][3] = f2tf32(As[s][mr + 8][kb + tig + 4]);
            }
            uint32_t b[8][2];
#pragma unroll
            for (int nt = 0; nt < 8; nt++) {
                int nc = warp_n + nt * 8 + g;
                b[nt][0] = f2tf32(Bs[s][kb + tig][nc]);
                b[nt][1] = f2tf32(Bs[s][kb + tig + 4][nc]);
            }
#pragma unroll
            for (int mt = 0; mt < 2; mt++)
#pragma unroll
                for (int nt = 0; nt < 8; nt++) {
                    asm volatile(
                        "mma.sync.aligned.m16n8k8.row.col.f32.tf32.tf32.f32 "
                        "{%0,%1,%2,%3}, {%4,%5,%6,%7}, {%8,%9}, {%0,%1,%2,%3};"
                        : "+f"(c[mt][nt][0]), "+f"(c[mt][nt][1]),
                          "+f"(c[mt][nt][2]), "+f"(c[mt][nt][3])
                        : "r"(a[mt][0]), "r"(a[mt][1]), "r"(a[mt][2]), "r"(a[mt][3]),
                          "r"(b[nt][0]), "r"(b[nt][1]));
                }
        }
        __syncthreads();
    }

#pragma unroll
    for (int nt = 0; nt < 8; nt++) {
        int col = n0 + warp_n + nt * 8 + tig * 2;
        float b0 = bias[col], b1 = bias[col + 1];
#pragma unroll
        for (int mt = 0; mt < 2; mt++) {
#pragma unroll
            for (int h = 0; h < 2; h++) {
                int row = row0 + warp_m + mt * 16 + g + h * 8;
                if (row < M) {
                    float o0 = alpha * c[mt][nt][h * 2 + 0] + b0;
                    float o1 = alpha * c[mt][nt][h * 2 + 1] + b1;
                    if (EPI == 1) { o0 = fmaxf(o0, 0.f); o1 = fmaxf(o1, 0.f); }
                    if (EPI == 2) {
                        const float* rp = resid + (size_t)row * ldC + col;
                        o0 += rp[0]; o1 += rp[1];
                    }
                    *(float2*)(C + (size_t)row * ldC + col) = make_float2(o0, o1);
                }
            }
        }
    }
}

// ---------------------------------------------------------------------------
// Host launch
// ---------------------------------------------------------------------------
extern "C" void kernel_launch(void* const* d_in, const int* in_sizes, int n_in,
                              void* d_out, int out_size) {
    const float* frame = (const float*)d_in[0];
    const float* fe    = (const float*)d_in[1];
    const int* s_ff = (const int*)d_in[2];  const int* d_ff = (const int*)d_in[3];
    const int* s_fE = (const int*)d_in[4];  const int* d_fE = (const int*)d_in[5];  // frfe
    const int* s_ef = (const int*)d_in[6];  const int* d_ef = (const int*)d_in[7];  // fefr
    const int* s_ee = (const int*)d_in[8];  const int* d_ee = (const int*)d_in[9];
    const float* W_fr_lin = (const float*)d_in[10]; const float* b_fr_lin = (const float*)d_in[11];
    const float* W_fe_lin = (const float*)d_in[12]; const float* b_fe_lin = (const float*)d_in[13];
    const float* W_frfr = (const float*)d_in[14];   const float* b_frfr = (const float*)d_in[15];
    const float* W_frfe = (const float*)d_in[16];   const float* b_frfe = (const float*)d_in[17];
    const float* W_fefr = (const float*)d_in[18];   const float* b_fefr = (const float*)d_in[19];
    const float* W_fefe = (const float*)d_in[20];   const float* b_fefe = (const float*)d_in[21];
    const float* W_fr_fc = (const float*)d_in[22];  const float* b_fr_fc = (const float*)d_in[23];
    const float* W_fe_fc = (const float*)d_in[24];  const float* b_fe_fc = (const float*)d_in[25];

    float *x_fr, *x_fe, *h_fr, *h_fe, *aggF, *aggE, *deg;
    float *WcatF, *WcatE, *bias_gF, *bias_gE;
    int *ideg, *csr_ff, *csr_ef, *csr_fE, *csr_ee;
    int *row_ff, *cur_ff, *row_ef, *cur_ef, *row_fE, *cur_fE, *row_ee, *cur_ee;
    int *part, *bsum;
    cudaGetSymbolAddress((void**)&x_fr, g_x_fr);
    cudaGetSymbolAddress((void**)&x_fe, g_x_fe);
    cudaGetSymbolAddress((void**)&h_fr, g_h_fr);
    cudaGetSymbolAddress((void**)&h_fe, g_h_fe);
    cudaGetSymbolAddress((void**)&aggF, g_aggF);
    cudaGetSymbolAddress((void**)&aggE, g_aggE);
    cudaGetSymbolAddress((void**)&deg, g_deg);
    cudaGetSymbolAddress((void**)&ideg, g_ideg);
    cudaGetSymbolAddress((void**)&WcatF, g_WcatF);
    cudaGetSymbolAddress((void**)&WcatE, g_WcatE);
    cudaGetSymbolAddress((void**)&bias_gF, g_bias_gF);
    cudaGetSymbolAddress((void**)&bias_gE, g_bias_gE);
    cudaGetSymbolAddress((void**)&csr_ff, g_csr_ff);
    cudaGetSymbolAddress((void**)&csr_ef, g_csr_ef);
    cudaGetSymbolAddress((void**)&csr_fE, g_csr_fE);
    cudaGetSymbolAddress((void**)&csr_ee, g_csr_ee);
    cudaGetSymbolAddress((void**)&row_ff, g_row_ff);
    cudaGetSymbolAddress((void**)&cur_ff, g_cur_ff);
    cudaGetSymbolAddress((void**)&row_ef, g_row_ef);
    cudaGetSymbolAddress((void**)&cur_ef, g_cur_ef);
    cudaGetSymbolAddress((void**)&row_fE, g_row_fE);
    cudaGetSymbolAddress((void**)&cur_fE, g_cur_fE);
    cudaGetSymbolAddress((void**)&row_ee, g_row_ee);
    cudaGetSymbolAddress((void**)&cur_ee, g_cur_ee);
    cudaGetSymbolAddress((void**)&part, g_part);
    cudaGetSymbolAddress((void**)&bsum, g_bsum);

    // int degree layout (matches float norm layout)
    int* id_out_ff = ideg;                           // ns_ff
    int* id_in_ff  = ideg + NF;                      // nd_ff
    int* id_out_fE = ideg + 2 * (size_t)NF;          // ns_fE
    int* id_in_ef  = ideg + 3 * (size_t)NF;          // nd_ef
    int* id_in_fE  = ideg + 4 * (size_t)NF;          // nd_fE
    int* id_out_ef = ideg + 4 * (size_t)NF + NE;     // ns_ef
    int* id_out_ee = ideg + 4 * (size_t)NF + 2 * (size_t)NE;
    int* id_in_ee  = ideg + 4 * (size_t)NF + 3 * (size_t)NE;

    float* ns_ff = deg;
    float* nd_ff = deg + NF;
    float* ns_fE = deg + 2 * (size_t)NF;
    float* nd_ef = deg + 3 * (size_t)NF;
    float* nd_fE = deg + 4 * (size_t)NF;
    float* ns_ef = deg + 4 * (size_t)NF + NE;
    float* ns_ee = deg + 4 * (size_t)NF + 2 * (size_t)NE;
    float* nd_ee = deg + 4 * (size_t)NF + 3 * (size_t)NE;

    float* out = (float*)d_out;
    float* o_frh = out;
    float* o_feh = out + (size_t)NF * RAW;
    float* o_hfr = o_feh + (size_t)NE * RAW;
    float* o_hfe = o_hfr + (size_t)NF * HID;

    const int T = 256;
    const size_t degN = (size_t)4 * NF + (size_t)4 * NE;

    // ---- weight prep ----
    concat_kernel<<<(256 * 128 + T - 1) / T, T>>>(W_frfr, W_fefr, WcatF);
    concat_kernel<<<(256 * 128 + T - 1) / T, T>>>(W_frfe, W_fefe, WcatE);
    bias_combine_kernel<<<1, 128>>>(b_frfr, b_fefr, bias_gF, 0.5f);
    bias_combine_kernel<<<1, 128>>>(b_frfe, b_fefe, bias_gE, 0.5f);

    // ---- degrees (int) & norms ----
    zero_kernel<<<(unsigned)((degN / 4 + T - 1) / T), T>>>((float*)ideg, degN / 4);
    int eb = (NEDGE + T - 1) / T;
    deg_kernel<<<eb, T>>>(s_ff, d_ff, id_out_ff, id_in_ff, NEDGE);
    deg_kernel<<<eb, T>>>(s_fE, d_fE, id_out_fE, id_in_fE, NEDGE);
    deg_kernel<<<eb, T>>>(s_ef, d_ef, id_out_ef, id_in_ef, NEDGE);
    deg_kernel<<<eb, T>>>(s_ee, d_ee, id_out_ee, id_in_ee, NEDGE);
    norm_kernel<<<(unsigned)((degN + T - 1) / T), T>>>(ideg, deg, (int)degN);

    // ---- CSR build (dst-sorted) per relation ----
    const int nbF = (NF + 255) / 256;   // 391
    const int nbE = (NE + 255) / 256;   // 782
    auto build = [&](const int* esrc, const int* edst, int* din,
                     int* row, int* cur, int* csr, int n, int nb) {
        scan_partial<<<nb, 256>>>(din, part, bsum, n);
        scan_bsum<<<1, 1024>>>(bsum, nb);
        scan_add<<<nb, 256>>>(part, bsum, row, cur, n);
        fill_kernel<<<eb, T>>>(esrc, edst, cur, csr, NEDGE);
    };
    build(s_ff, d_ff, id_in_ff, row_ff, cur_ff, csr_ff, NF, nbF);
    build(s_ef, d_ef, id_in_ef, row_ef, cur_ef, csr_ef, NF, nbF);
    build(s_fE, d_fE, id_in_fE, row_fE, cur_fE, csr_fE, NE, nbE);
    build(s_ee, d_ee, id_in_ee, row_ee, cur_ee, csr_ee, NE, nbE);

    const unsigned gFx = (NF + 127) / 128;   // 782
    const unsigned gEx = (NE + 127) / 128;   // 1563

    // ---- input linears (K=512, N=128) ----
    mma_gemm<0><<<dim3(gFx, 1), 256>>>(frame, W_fr_lin, b_fr_lin, nullptr,
                                       x_fr, NF, RAW, HID, HID, 1.f);
    mma_gemm<0><<<dim3(gEx, 1), 256>>>(fe, W_fe_lin, b_fe_lin, nullptr,
                                       x_fe, NE, RAW, HID, HID, 1.f);

    const unsigned gwF = (NF * 32 + T - 1) / T;   // warp per node
    const unsigned gwE = (NE * 32 + T - 1) / T;

    // ---- layer 1 ----
    gather_kernel<<<gwF, T>>>(x_fr, csr_ff, row_ff, id_in_ff, ns_ff, nd_ff,
                              x_fe, csr_ef, row_ef, id_in_ef, ns_ef, nd_ef,
                              aggF, NF);
    gather_kernel<<<gwE, T>>>(x_fr, csr_fE, row_fE, id_in_fE, ns_fE, nd_fE,
                              x_fe, csr_ee, row_ee, id_in_ee, ns_ee, nd_ee,
                              aggE, NE);
    mma_gemm<1><<<dim3(gFx, 1), 256>>>(aggF, WcatF, bias_gF, nullptr,
                                       h_fr, NF, 256, HID, HID, 0.5f);
    mma_gemm<1><<<dim3(gEx, 1), 256>>>(aggE, WcatE, bias_gE, nullptr,
                                       h_fe, NE, 256, HID, HID, 0.5f);

    // ---- layer 2 ----
    gather_kernel<<<gwF, T>>>(h_fr, csr_ff, row_ff, id_in_ff, ns_ff, nd_ff,
                              h_fe, csr_ef, row_ef, id_in_ef, ns_ef, nd_ef,
                              aggF, NF);
    gather_kernel<<<gwE, T>>>(h_fr, csr_fE, row_fE, id_in_fE, ns_fE, nd_fE,
                              h_fe, csr_ee, row_ee, id_in_ee, ns_ee, nd_ee,
                              aggE, NE);
    mma_gemm<2><<<dim3(gFx, 1), 256>>>(aggF, WcatF, bias_gF, x_fr,
                                       o_hfr, NF, 256, HID, HID, 0.5f);
    mma_gemm<2><<<dim3(gEx, 1), 256>>>(aggE, WcatE, bias_gE, x_fe,
                                       o_hfe, NE, 256, HID, HID, 0.5f);

    // ---- output FCs (K=128, N=512) ----
    mma_gemm<0><<<dim3(gFx, 4), 256>>>(o_hfr, W_fr_fc, b_fr_fc, nullptr,
                                       o_frh, NF, HID, RAW, RAW, 1.f);
    mma_gemm<0><<<dim3(gEx, 4), 256>>>(o_hfe, W_fe_fc, b_fe_fc, nullptr,
                                       o_feh, NE, HID, RAW, RAW, 1.f);
}

// round 5
// speedup vs baseline: 1.6885x; 1.6885x over previous
#include <cuda_runtime.h>
#include <cuda_fp16.h>
#include <cstdint>
#include <cstddef>

// ---------------------------------------------------------------------------
// Problem constants
// ---------------------------------------------------------------------------
#define NF 100000
#define NE 200000
#define HID 128
#define RAW 512
#define NEDGE 1000000

// ---------------------------------------------------------------------------
// Scratch (device globals -- no allocation allowed)
// ---------------------------------------------------------------------------
__device__ __half g_frame_h[(size_t)NF * RAW];
__device__ __half g_fe_h[(size_t)NE * RAW];
__device__ float  g_x_fr32[(size_t)NF * HID];
__device__ float  g_x_fe32[(size_t)NE * HID];
__device__ __half g_x_fr16[(size_t)NF * HID];
__device__ __half g_x_fe16[(size_t)NE * HID];
__device__ __half g_h_fr16[(size_t)NF * HID];     // layer-1 output (relu)
__device__ __half g_h_fe16[(size_t)NE * HID];
__device__ __half g_h2_fr16[(size_t)NF * HID];    // layer-2 output half copy
__device__ __half g_h2_fe16[(size_t)NE * HID];
__device__ __half g_aggF[(size_t)NF * 256];       // [FF | EF]
__device__ __half g_aggE[(size_t)NE * 256];       // [FE | EE]
__device__ int    g_ideg[(size_t)4 * NF + (size_t)4 * NE];
__device__ float  g_deg[(size_t)4 * NF + (size_t)4 * NE];
// fp16 transposed weights, [N][K] k-major
__device__ __half g_WlinF_t[(size_t)HID * RAW];
__device__ __half g_WlinE_t[(size_t)HID * RAW];
__device__ __half g_WcatF_t[(size_t)HID * 256];
__device__ __half g_WcatE_t[(size_t)HID * 256];
__device__ __half g_WfcF_t[(size_t)RAW * HID];
__device__ __half g_WfcE_t[(size_t)RAW * HID];
__device__ float  g_bias_gF[HID];
__device__ float  g_bias_gE[HID];
// CSR (dst-sorted src lists) per relation
__device__ int g_csr_ff[NEDGE];
__device__ int g_csr_ef[NEDGE];
__device__ int g_csr_fE[NEDGE];
__device__ int g_csr_ee[NEDGE];
__device__ int g_row_ff[NF];  __device__ int g_cur_ff[NF];
__device__ int g_row_ef[NF];  __device__ int g_cur_ef[NF];
__device__ int g_row_fE[NE];  __device__ int g_cur_fE[NE];
__device__ int g_row_ee[NE];  __device__ int g_cur_ee[NE];
__device__ int g_part[NE];
__device__ int g_bsum[1024];

// ---------------------------------------------------------------------------
// Helpers
// ---------------------------------------------------------------------------
__device__ __forceinline__ uint32_t smem_u32(const void* p) {
    uint32_t r;
    asm("{ .reg .u64 t; cvta.to.shared.u64 t, %1; cvt.u32.u64 %0, t; }"
        : "=r"(r) : "l"(p));
    return r;
}

// ---------------------------------------------------------------------------
// Utility kernels
// ---------------------------------------------------------------------------
__global__ void zero_kernel(float* __restrict__ p, size_t n4) {
    size_t i = (size_t)blockIdx.x * blockDim.x + threadIdx.x;
    if (i < n4) ((float4*)p)[i] = make_float4(0.f, 0.f, 0.f, 0.f);
}

__global__ void f2h_kernel(const float* __restrict__ in, __half* __restrict__ out,
                           size_t n4) {
    size_t i = (size_t)blockIdx.x * blockDim.x + threadIdx.x;
    if (i < n4) {
        float4 v = ((const float4*)in)[i];
        __half2 a = __floats2half2_rn(v.x, v.y);
        __half2 b = __floats2half2_rn(v.z, v.w);
        ((uint2*)out)[i] = make_uint2(*(uint32_t*)&a, *(uint32_t*)&b);
    }
}

// out_h[n*K + k] = (half) W[k*N + n]
__global__ void wtrans_kernel(const float* __restrict__ W, __half* __restrict__ out,
                              int K, int N) {
    int idx = blockIdx.x * blockDim.x + threadIdx.x;
    if (idx < K * N) {
        int n = idx / K, k = idx % K;
        out[idx] = __float2half(W[(size_t)k * N + n]);
    }
}

// out_h[n*256 + k]: k<128 -> W1[k][n], else W2[k-128][n]
__global__ void wcat_trans_kernel(const float* __restrict__ W1,
                                  const float* __restrict__ W2,
                                  __half* __restrict__ out) {
    int idx = blockIdx.x * blockDim.x + threadIdx.x;
    if (idx < 128 * 256) {
        int n = idx >> 8, k = idx & 255;
        float v = (k < 128) ? W1[(size_t)k * 128 + n] : W2[(size_t)(k - 128) * 128 + n];
        out[idx] = __float2half(v);
    }
}

__global__ void bias_combine_kernel(const float* __restrict__ b1,
                                    const float* __restrict__ b2,
                                    float* __restrict__ out, float alpha) {
    int i = blockIdx.x * blockDim.x + threadIdx.x;
    if (i < HID) out[i] = alpha * (b1[i] + b2[i]);
}

__global__ void deg_kernel(const int* __restrict__ src, const int* __restrict__ dst,
                           int* __restrict__ dout, int* __restrict__ din, int n) {
    int i = blockIdx.x * blockDim.x + threadIdx.x;
    if (i < n) {
        atomicAdd(&dout[src[i]], 1);
        atomicAdd(&din[dst[i]], 1);
    }
}

__global__ void norm_kernel(const int* __restrict__ d, float* __restrict__ p, int n) {
    int i = blockIdx.x * blockDim.x + threadIdx.x;
    if (i < n) {
        int v = d[i];
        p[i] = (v > 0) ? rsqrtf((float)v) : 0.f;
    }
}

// ---------------------------------------------------------------------------
// Exclusive scan (3-phase) for row offsets; nb <= 1024
// ---------------------------------------------------------------------------
__global__ void scan_partial(const int* __restrict__ in, int* __restrict__ part,
                             int* __restrict__ bsum, int n) {
    __shared__ int sh[256];
    int t = threadIdx.x;
    int i = blockIdx.x * 256 + t;
    int v = (i < n) ? in[i] : 0;
    sh[t] = v;
    __syncthreads();
#pragma unroll
    for (int off = 1; off < 256; off <<= 1) {
        int u = (t >= off) ? sh[t - off] : 0;
        __syncthreads();
        sh[t] += u;
        __syncthreads();
    }
    if (i < n) part[i] = sh[t] - v;
    if (t == 255) bsum[blockIdx.x] = sh[255];
}

__global__ void scan_bsum(int* __restrict__ bsum, int nb) {
    __shared__ int sh[1024];
    int t = threadIdx.x;
    int v = (t < nb) ? bsum[t] : 0;
    sh[t] = v;
    __syncthreads();
#pragma unroll
    for (int off = 1; off < 1024; off <<= 1) {
        int u = (t >= off) ? sh[t - off] : 0;
        __syncthreads();
        sh[t] += u;
        __syncthreads();
    }
    if (t < nb) bsum[t] = sh[t] - v;
}

__global__ void scan_add(const int* __restrict__ part, const int* __restrict__ bsum,
                         int* __restrict__ row, int* __restrict__ cur, int n) {
    int i = blockIdx.x * 256 + threadIdx.x;
    if (i < n) {
        int v = part[i] + bsum[blockIdx.x];
        row[i] = v;
        cur[i] = v;
    }
}

__global__ void fill_kernel(const int* __restrict__ src, const int* __restrict__ dst,
                            int* __restrict__ cur, int* __restrict__ csr, int n) {
    int i = blockIdx.x * blockDim.x + threadIdx.x;
    if (i < n) {
        int pos = atomicAdd(&cur[dst[i]], 1);
        csr[pos] = src[i];
    }
}

// ---------------------------------------------------------------------------
// Gather aggregation (fp16 in / fp32 accum / fp16 out), one warp per dst node.
// agg[i][0:128]   = nd1[i] * sum x1[s]*ns1[s]     (rel 1)
// agg[i][128:256] = nd2[i] * sum x2[s]*ns2[s]     (rel 2)
// Each lane owns 4 consecutive halfs (8B) of the 128-wide row.
// ---------------------------------------------------------------------------
__global__ void __launch_bounds__(256)
gather_kernel(const __half* __restrict__ x1, const int* __restrict__ csr1,
              const int* __restrict__ row1, const int* __restrict__ deg1,
              const float* __restrict__ ns1, const float* __restrict__ nd1,
              const __half* __restrict__ x2, const int* __restrict__ csr2,
              const int* __restrict__ row2, const int* __restrict__ deg2,
              const float* __restrict__ ns2, const float* __restrict__ nd2,
              __half* __restrict__ agg, int n) {
    int warp = (blockIdx.x * blockDim.x + threadIdx.x) >> 5;
    if (warp >= n) return;
    int lane = threadIdx.x & 31;

    float4 a1 = make_float4(0.f, 0.f, 0.f, 0.f);
    {
        int start = row1[warp], dc = deg1[warp];
        for (int base = 0; base < dc; base += 32) {
            int e = base + lane;
            int sidx = 0; float wv = 0.f;
            if (e < dc) { sidx = csr1[start + e]; wv = __ldg(&ns1[sidx]); }
            int m = min(32, dc - base);
            for (int j = 0; j < m; j++) {
                int s = __shfl_sync(0xffffffffu, sidx, j);
                float w = __shfl_sync(0xffffffffu, wv, j);
                uint2 raw = __ldg(&((const uint2*)(x1 + (size_t)s * HID))[lane]);
                float2 f0 = __half22float2(*(__half2*)&raw.x);
                float2 f1 = __half22float2(*(__half2*)&raw.y);
                a1.x += f0.x * w; a1.y += f0.y * w;
                a1.z += f1.x * w; a1.w += f1.y * w;
            }
        }
        float s1 = nd1[warp];
        a1.x *= s1; a1.y *= s1; a1.z *= s1; a1.w *= s1;
    }
    float4 a2 = make_float4(0.f, 0.f, 0.f, 0.f);
    {
        int start = row2[warp], dc = deg2[warp];
        for (int base = 0; base < dc; base += 32) {
            int e = base + lane;
            int sidx = 0; float wv = 0.f;
            if (e < dc) { sidx = csr2[start + e]; wv = __ldg(&ns2[sidx]); }
            int m = min(32, dc - base);
            for (int j = 0; j < m; j++) {
                int s = __shfl_sync(0xffffffffu, sidx, j);
                float w = __shfl_sync(0xffffffffu, wv, j);
                uint2 raw = __ldg(&((const uint2*)(x2 + (size_t)s * HID))[lane]);
                float2 f0 = __half22float2(*(__half2*)&raw.x);
                float2 f1 = __half22float2(*(__half2*)&raw.y);
                a2.x += f0.x * w; a2.y += f0.y * w;
                a2.z += f1.x * w; a2.w += f1.y * w;
            }
        }
        float s2 = nd2[warp];
        a2.x *= s2; a2.y *= s2; a2.z *= s2; a2.w *= s2;
    }
    __half* ap = agg + (size_t)warp * 256;
    __half2 p0 = __floats2half2_rn(a1.x, a1.y);
    __half2 p1 = __floats2half2_rn(a1.z, a1.w);
    ((uint2*)ap)[lane] = make_uint2(*(uint32_t*)&p0, *(uint32_t*)&p1);
    __half2 q0 = __floats2half2_rn(a2.x, a2.y);
    __half2 q1 = __floats2half2_rn(a2.z, a2.w);
    ((uint2*)(ap + 128))[lane] = make_uint2(*(uint32_t*)&q0, *(uint32_t*)&q1);
}

// ---------------------------------------------------------------------------
// FP16 mma.sync GEMM:  out = epi( alpha * (A @ B^T) + bias )
//   A: [M][K] half row-major.  B: [Ntot][K] half k-major (pre-transposed W).
// Tile 128x128, BK=32, 8 warps (each 32x64), cp.async double buffer.
// EPI: 0 = none, 1 = relu, 2 = +resid(fp32)
// OUTF: write fp32 to Cf (ld ldC); OUTH: write half to Ch (ld ldC)
// ---------------------------------------------------------------------------
template <int EPI, bool OUTF, bool OUTH>
__global__ void __launch_bounds__(256, 2)
mma_gemm(const __half* __restrict__ A, const __half* __restrict__ B,
         const float* __restrict__ bias, const float* __restrict__ resid,
         float* __restrict__ Cf, __half* __restrict__ Ch,
         int M, int K, int ldC, float alpha) {
    __shared__ __align__(16) __half As[2][128][40];   // 80B rows
    __shared__ __align__(16) __half Bs[2][128][40];

    const int tid = threadIdx.x;
    const int wid = tid >> 5;
    const int lane = tid & 31;
    const int g = lane >> 2;
    const int tig = lane & 3;
    const int warp_m = (wid & 3) * 32;
    const int warp_n = (wid >> 2) * 64;
    const int row0 = blockIdx.x * 128;
    const int n0 = blockIdx.y * 128;
    const __half* Bt = B + (size_t)n0 * K;

    float c[2][8][4];
#pragma unroll
    for (int mt = 0; mt < 2; mt++)
#pragma unroll
        for (int nt = 0; nt < 8; nt++)
#pragma unroll
            for (int q = 0; q < 4; q++) c[mt][nt][q] = 0.f;

    const int NIT = K >> 5;    // BK = 32

    auto load_stage = [&](int s, int k0) {
        // A: 128 rows x 32 halfs (4 x 16B chunks) = 512 chunks
#pragma unroll
        for (int i = 0; i < 2; i++) {
            int cid = tid + i * 256;
            int m = cid >> 2, kc = (cid & 3) << 3;   // halfs
            const __half* src = A + (size_t)(row0 + m) * K + k0 + kc;
            uint32_t dst = smem_u32(&As[s][m][kc]);
            unsigned sz = (row0 + m < M) ? 16u : 0u;
            asm volatile("cp.async.cg.shared.global [%0], [%1], 16, %2;"
                         :: "r"(dst), "l"(src), "r"(sz));
        }
        // B: 128 n-rows x 32 halfs
#pragma unroll
        for (int i = 0; i < 2; i++) {
            int cid = tid + i * 256;
            int nn = cid >> 2, kc = (cid & 3) << 3;
            const __half* src = Bt + (size_t)nn * K + k0 + kc;
            uint32_t dst = smem_u32(&Bs[s][nn][kc]);
            asm volatile("cp.async.cg.shared.global [%0], [%1], 16;"
                         :: "r"(dst), "l"(src));
        }
        asm volatile("cp.async.commit_group;");
    };

    load_stage(0, 0);

    for (int it = 0; it < NIT; it++) {
        int s = it & 1;
        if (it + 1 < NIT) {
            load_stage(s ^ 1, (it + 1) << 5);
            asm volatile("cp.async.wait_group 1;");
        } else {
            asm volatile("cp.async.wait_group 0;");
        }
        __syncthreads();

#pragma unroll
        for (int ks = 0; ks < 2; ks++) {            // two k16 steps
            const int kb = ks << 4;
            uint32_t a[2][4];
#pragma unroll
            for (int mt = 0; mt < 2; mt++) {
                int mr = warp_m + mt * 16 + g;
                a[mt][0] = *(const uint32_t*)&As[s][mr][kb + 2 * tig];
                a[mt][1] = *(const uint32_t*)&As[s][mr + 8][kb + 2 * tig];
                a[mt][2] = *(const uint32_t*)&As[s][mr][kb + 2 * tig + 8];
                a[mt][3] = *(const uint32_t*)&As[s][mr + 8][kb + 2 * tig + 8];
            }
            uint32_t b[8][2];
#pragma unroll
            for (int nt = 0; nt < 8; nt++) {
                int nc = warp_n + nt * 8 + g;
                b[nt][0] = *(const uint32_t*)&Bs[s][nc][kb + 2 * tig];
                b[nt][1] = *(const uint32_t*)&Bs[s][nc][kb + 2 * tig + 8];
            }
#pragma unroll
            for (int mt = 0; mt < 2; mt++)
#pragma unroll
                for (int nt = 0; nt < 8; nt++) {
                    asm volatile(
                        "mma.sync.aligned.m16n8k16.row.col.f32.f16.f16.f32 "
                        "{%0,%1,%2,%3}, {%4,%5,%6,%7}, {%8,%9}, {%0,%1,%2,%3};"
                        : "+f"(c[mt][nt][0]), "+f"(c[mt][nt][1]),
                          "+f"(c[mt][nt][2]), "+f"(c[mt][nt][3])
                        : "r"(a[mt][0]), "r"(a[mt][1]), "r"(a[mt][2]), "r"(a[mt][3]),
                          "r"(b[nt][0]), "r"(b[nt][1]));
                }
        }
        __syncthreads();
    }

    // ---- epilogue ----
#pragma unroll
    for (int nt = 0; nt < 8; nt++) {
        int col = n0 + warp_n + nt * 8 + tig * 2;
        float b0 = bias[col], b1 = bias[col + 1];
#pragma unroll
        for (int mt = 0; mt < 2; mt++) {
#pragma unroll
            for (int h = 0; h < 2; h++) {
                int row = row0 + warp_m + mt * 16 + g + h * 8;
                if (row < M) {
                    float o0 = alpha * c[mt][nt][h * 2 + 0] + b0;
                    float o1 = alpha * c[mt][nt][h * 2 + 1] + b1;
                    if (EPI == 1) { o0 = fmaxf(o0, 0.f); o1 = fmaxf(o1, 0.f); }
                    if (EPI == 2) {
                        const float* rp = resid + (size_t)row * ldC + col;
                        o0 += rp[0]; o1 += rp[1];
                    }
                    if (OUTF)
                        *(float2*)(Cf + (size_t)row * ldC + col) = make_float2(o0, o1);
                    if (OUTH)
                        *(__half2*)(Ch + (size_t)row * ldC + col) =
                            __floats2half2_rn(o0, o1);
                }
            }
        }
    }
}

// ---------------------------------------------------------------------------
// Host launch
// ---------------------------------------------------------------------------
extern "C" void kernel_launch(void* const* d_in, const int* in_sizes, int n_in,
                              void* d_out, int out_size) {
    const float* frame = (const float*)d_in[0];
    const float* fe    = (const float*)d_in[1];
    const int* s_ff = (const int*)d_in[2];  const int* d_ff = (const int*)d_in[3];
    const int* s_fE = (const int*)d_in[4];  const int* d_fE = (const int*)d_in[5];  // frfe
    const int* s_ef = (const int*)d_in[6];  const int* d_ef = (const int*)d_in[7];  // fefr
    const int* s_ee = (const int*)d_in[8];  const int* d_ee = (const int*)d_in[9];
    const float* W_fr_lin = (const float*)d_in[10]; const float* b_fr_lin = (const float*)d_in[11];
    const float* W_fe_lin = (const float*)d_in[12]; const float* b_fe_lin = (const float*)d_in[13];
    const float* W_frfr = (const float*)d_in[14];   const float* b_frfr = (const float*)d_in[15];
    const float* W_frfe = (const float*)d_in[16];   const float* b_frfe = (const float*)d_in[17];
    const float* W_fefr = (const float*)d_in[18];   const float* b_fefr = (const float*)d_in[19];
    const float* W_fefe = (const float*)d_in[20];   const float* b_fefe = (const float*)d_in[21];
    const float* W_fr_fc = (const float*)d_in[22];  const float* b_fr_fc = (const float*)d_in[23];
    const float* W_fe_fc = (const float*)d_in[24];  const float* b_fe_fc = (const float*)d_in[25];

    __half *frame_h, *fe_h, *x_fr16, *x_fe16, *h_fr16, *h_fe16, *h2_fr16, *h2_fe16;
    __half *aggF, *aggE;
    __half *WlinF_t, *WlinE_t, *WcatF_t, *WcatE_t, *WfcF_t, *WfcE_t;
    float *x_fr32, *x_fe32, *deg, *bias_gF, *bias_gE;
    int *ideg, *csr_ff, *csr_ef, *csr_fE, *csr_ee;
    int *row_ff, *cur_ff, *row_ef, *cur_ef, *row_fE, *cur_fE, *row_ee, *cur_ee;
    int *part, *bsum;
    cudaGetSymbolAddress((void**)&frame_h, g_frame_h);
    cudaGetSymbolAddress((void**)&fe_h, g_fe_h);
    cudaGetSymbolAddress((void**)&x_fr32, g_x_fr32);
    cudaGetSymbolAddress((void**)&x_fe32, g_x_fe32);
    cudaGetSymbolAddress((void**)&x_fr16, g_x_fr16);
    cudaGetSymbolAddress((void**)&x_fe16, g_x_fe16);
    cudaGetSymbolAddress((void**)&h_fr16, g_h_fr16);
    cudaGetSymbolAddress((void**)&h_fe16, g_h_fe16);
    cudaGetSymbolAddress((void**)&h2_fr16, g_h2_fr16);
    cudaGetSymbolAddress((void**)&h2_fe16, g_h2_fe16);
    cudaGetSymbolAddress((void**)&aggF, g_aggF);
    cudaGetSymbolAddress((void**)&aggE, g_aggE);
    cudaGetSymbolAddress((void**)&ideg, g_ideg);
    cudaGetSymbolAddress((void**)&deg, g_deg);
    cudaGetSymbolAddress((void**)&WlinF_t, g_WlinF_t);
    cudaGetSymbolAddress((void**)&WlinE_t, g_WlinE_t);
    cudaGetSymbolAddress((void**)&WcatF_t, g_WcatF_t);
    cudaGetSymbolAddress((void**)&WcatE_t, g_WcatE_t);
    cudaGetSymbolAddress((void**)&WfcF_t, g_WfcF_t);
    cudaGetSymbolAddress((void**)&WfcE_t, g_WfcE_t);
    cudaGetSymbolAddress((void**)&bias_gF, g_bias_gF);
    cudaGetSymbolAddress((void**)&bias_gE, g_bias_gE);
    cudaGetSymbolAddress((void**)&csr_ff, g_csr_ff);
    cudaGetSymbolAddress((void**)&csr_ef, g_csr_ef);
    cudaGetSymbolAddress((void**)&csr_fE, g_csr_fE);
    cudaGetSymbolAddress((void**)&csr_ee, g_csr_ee);
    cudaGetSymbolAddress((void**)&row_ff, g_row_ff);
    cudaGetSymbolAddress((void**)&cur_ff, g_cur_ff);
    cudaGetSymbolAddress((void**)&row_ef, g_row_ef);
    cudaGetSymbolAddress((void**)&cur_ef, g_cur_ef);
    cudaGetSymbolAddress((void**)&row_fE, g_row_fE);
    cudaGetSymbolAddress((void**)&cur_fE, g_cur_fE);
    cudaGetSymbolAddress((void**)&row_ee, g_row_ee);
    cudaGetSymbolAddress((void**)&cur_ee, g_cur_ee);
    cudaGetSymbolAddress((void**)&part, g_part);
    cudaGetSymbolAddress((void**)&bsum, g_bsum);

    // degree layout
    int* id_out_ff = ideg;
    int* id_in_ff  = ideg + NF;
    int* id_out_fE = ideg + 2 * (size_t)NF;
    int* id_in_ef  = ideg + 3 * (size_t)NF;
    int* id_in_fE  = ideg + 4 * (size_t)NF;
    int* id_out_ef = ideg + 4 * (size_t)NF + NE;
    int* id_out_ee = ideg + 4 * (size_t)NF + 2 * (size_t)NE;
    int* id_in_ee  = ideg + 4 * (size_t)NF + 3 * (size_t)NE;

    float* ns_ff = deg;
    float* nd_ff = deg + NF;
    float* ns_fE = deg + 2 * (size_t)NF;
    float* nd_ef = deg + 3 * (size_t)NF;
    float* nd_fE = deg + 4 * (size_t)NF;
    float* ns_ef = deg + 4 * (size_t)NF + NE;
    float* ns_ee = deg + 4 * (size_t)NF + 2 * (size_t)NE;
    float* nd_ee = deg + 4 * (size_t)NF + 3 * (size_t)NE;

    float* out = (float*)d_out;
    float* o_frh = out;
    float* o_feh = out + (size_t)NF * RAW;
    float* o_hfr = o_feh + (size_t)NE * RAW;
    float* o_hfe = o_hfr + (size_t)NF * HID;

    const int T = 256;
    const size_t degN = (size_t)4 * NF + (size_t)4 * NE;

    // ---- prep: fp16 conversions & weight transposes ----
    f2h_kernel<<<(unsigned)(((size_t)NF * RAW / 4 + T - 1) / T), T>>>(
        frame, frame_h, (size_t)NF * RAW / 4);
    f2h_kernel<<<(unsigned)(((size_t)NE * RAW / 4 + T - 1) / T), T>>>(
        fe, fe_h, (size_t)NE * RAW / 4);
    wtrans_kernel<<<(RAW * HID + T - 1) / T, T>>>(W_fr_lin, WlinF_t, RAW, HID);
    wtrans_kernel<<<(RAW * HID + T - 1) / T, T>>>(W_fe_lin, WlinE_t, RAW, HID);
    wcat_trans_kernel<<<(128 * 256 + T - 1) / T, T>>>(W_frfr, W_fefr, WcatF_t);
    wcat_trans_kernel<<<(128 * 256 + T - 1) / T, T>>>(W_frfe, W_fefe, WcatE_t);
    wtrans_kernel<<<(HID * RAW + T - 1) / T, T>>>(W_fr_fc, WfcF_t, HID, RAW);
    wtrans_kernel<<<(HID * RAW + T - 1) / T, T>>>(W_fe_fc, WfcE_t, HID, RAW);
    bias_combine_kernel<<<1, 128>>>(b_frfr, b_fefr, bias_gF, 0.5f);
    bias_combine_kernel<<<1, 128>>>(b_frfe, b_fefe, bias_gE, 0.5f);

    // ---- degrees (int) & norms ----
    zero_kernel<<<(unsigned)((degN / 4 + T - 1) / T), T>>>((float*)ideg, degN / 4);
    int eb = (NEDGE + T - 1) / T;
    deg_kernel<<<eb, T>>>(s_ff, d_ff, id_out_ff, id_in_ff, NEDGE);
    deg_kernel<<<eb, T>>>(s_fE, d_fE, id_out_fE, id_in_fE, NEDGE);
    deg_kernel<<<eb, T>>>(s_ef, d_ef, id_out_ef, id_in_ef, NEDGE);
    deg_kernel<<<eb, T>>>(s_ee, d_ee, id_out_ee, id_in_ee, NEDGE);
    norm_kernel<<<(unsigned)((degN + T - 1) / T), T>>>(ideg, deg, (int)degN);

    // ---- CSR build (dst-sorted) per relation ----
    const int nbF = (NF + 255) / 256;
    const int nbE = (NE + 255) / 256;
    auto build = [&](const int* esrc, const int* edst, int* din,
                     int* row, int* cur, int* csr, int n, int nb) {
        scan_partial<<<nb, 256>>>(din, part, bsum, n);
        scan_bsum<<<1, 1024>>>(bsum, nb);
        scan_add<<<nb, 256>>>(part, bsum, row, cur, n);
        fill_kernel<<<eb, T>>>(esrc, edst, cur, csr, NEDGE);
    };
    build(s_ff, d_ff, id_in_ff, row_ff, cur_ff, csr_ff, NF, nbF);
    build(s_ef, d_ef, id_in_ef, row_ef, cur_ef, csr_ef, NF, nbF);
    build(s_fE, d_fE, id_in_fE, row_fE, cur_fE, csr_fE, NE, nbE);
    build(s_ee, d_ee, id_in_ee, row_ee, cur_ee, csr_ee, NE, nbE);

    const unsigned gFx = (NF + 127) / 128;
    const unsigned gEx = (NE + 127) / 128;

    // ---- input linears (K=512, N=128): x fp32 + fp16 ----
    mma_gemm<0, true, true><<<dim3(gFx, 1), 256>>>(
        frame_h, WlinF_t, b_fr_lin, nullptr, x_fr32, x_fr16, NF, RAW, HID, 1.f);
    mma_gemm<0, true, true><<<dim3(gEx, 1), 256>>>(
        fe_h, WlinE_t, b_fe_lin, nullptr, x_fe32, x_fe16, NE, RAW, HID, 1.f);

    const unsigned gwF = (NF * 32 + T - 1) / T;
    const unsigned gwE = (NE * 32 + T - 1) / T;

    // ---- layer 1 ----
    gather_kernel<<<gwF, T>>>(x_fr16, csr_ff, row_ff, id_in_ff, ns_ff, nd_ff,
                              x_fe16, csr_ef, row_ef, id_in_ef, ns_ef, nd_ef,
                              aggF, NF);
    gather_kernel<<<gwE, T>>>(x_fr16, csr_fE, row_fE, id_in_fE, ns_fE, nd_fE,
                              x_fe16, csr_ee, row_ee, id_in_ee, ns_ee, nd_ee,
                              aggE, NE);
    mma_gemm<1, false, true><<<dim3(gFx, 1), 256>>>(
        aggF, WcatF_t, bias_gF, nullptr, nullptr, h_fr16, NF, 256, HID, 0.5f);
    mma_gemm<1, false, true><<<dim3(gEx, 1), 256>>>(
        aggE, WcatE_t, bias_gE, nullptr, nullptr, h_fe16, NE, 256, HID, 0.5f);

    // ---- layer 2 (fp32 h -> d_out, half copy for fc) ----
    gather_kernel<<<gwF, T>>>(h_fr16, csr_ff, row_ff, id_in_ff, ns_ff, nd_ff,
                              h_fe16, csr_ef, row_ef, id_in_ef, ns_ef, nd_ef,
                              aggF, NF);
    gather_kernel<<<gwE, T>>>(h_fr16, csr_fE, row_fE, id_in_fE, ns_fE, nd_fE,
                              h_fe16, csr_ee, row_ee, id_in_ee, ns_ee, nd_ee,
                              aggE, NE);
    mma_gemm<2, true, true><<<dim3(gFx, 1), 256>>>(
        aggF, WcatF_t, bias_gF, x_fr32, o_hfr, h2_fr16, NF, 256, HID, 0.5f);
    mma_gemm<2, true, true><<<dim3(gEx, 1), 256>>>(
        aggE, WcatE_t, bias_gE, x_fe32, o_hfe, h2_fe16, NE, 256, HID, 0.5f);

    // ---- output FCs (K=128, N=512) ----
    mma_gemm<0, true, false><<<dim3(gFx, 4), 256>>>(
        h2_fr16, WfcF_t, b_fr_fc, nullptr, o_frh, nullptr, NF, HID, RAW, 1.f);
    mma_gemm<0, true, false><<<dim3(gEx, 4), 256>>>(
        h2_fe16, WfcE_t, b_fe_fc, nullptr, o_feh, nullptr, NE, HID, RAW, 1.f);
}